// round 1
// baseline (speedup 1.0000x reference)
#include <cuda_runtime.h>
#include <cuda_bf16.h>

#define B_  256
#define K_  500
#define H_  152
#define W_  272
#define HW_ (H_ * W_)
#define HASH_SIZE 1024
#define NTHREADS 512

__device__ float g_pnum[B_];
__device__ float g_pmask[B_];

__device__ __forceinline__ unsigned hash_id(int id) {
    return ((unsigned)id * 2654435761u) & (HASH_SIZE - 1);
}

__global__ __launch_bounds__(NTHREADS) void fwd_loss_main(
    const float* __restrict__ flow,   // [B,2,H,W]
    const float* __restrict__ mask,   // [B,K]
    const int*   __restrict__ index,  // [B,K]
    const int*   __restrict__ ids,    // [B,K]
    const int*   __restrict__ index2, // [B,K]
    const int*   __restrict__ ids2)   // [B,K]
{
    __shared__ int   hkey[HASH_SIZE];
    __shared__ int   hval[HASH_SIZE];
    __shared__ float red_num[NTHREADS / 32];
    __shared__ float red_msk[NTHREADS / 32];

    const int b   = blockIdx.x;
    const int tid = threadIdx.x;

    for (int i = tid; i < HASH_SIZE; i += NTHREADS) hkey[i] = 0;
    __syncthreads();

    // Build hash: id -> position x. ids are unique & nonzero per batch element.
    for (int k = tid; k < K_; k += NTHREADS) {
        int id = ids[b * K_ + k];
        unsigned slot = hash_id(id);
        while (true) {
            int old = atomicCAS(&hkey[slot], 0, id);
            if (old == 0) { hval[slot] = k; break; }
            slot = (slot + 1) & (HASH_SIZE - 1);
        }
    }
    __syncthreads();

    const float* fb = flow + (size_t)b * 2 * HW_;

    float lnum = 0.0f, lmask = 0.0f;
    for (int j = tid; j < K_; j += NTHREADS) {
        lmask += mask[b * K_ + j];

        int id2 = ids2[b * K_ + j];
        if (id2 != 0) {
            unsigned slot = hash_id(id2);
            int x = -1;
            while (true) {
                int key = hkey[slot];
                if (key == id2) { x = hval[slot]; break; }
                if (key == 0) break;  // not present (e.g. the +100000 ids)
                slot = (slot + 1) & (HASH_SIZE - 1);
            }
            if (x >= 0) {
                float m = mask[b * K_ + x];
                int   p = index[b * K_ + x];
                float px = fb[p] * m;          // channel 0
                float py = fb[HW_ + p] * m;    // channel 1
                int   i2 = index2[b * K_ + j];
                float vx = (float)(i2 % W_);
                float vy = (float)i2 / (float)W_;
                lnum += fabsf(px - vx) + fabsf(py - vy);
            }
        }
    }

    // Block reduction of (lnum, lmask)
    const int lane = tid & 31;
    const int warp = tid >> 5;
    #pragma unroll
    for (int off = 16; off > 0; off >>= 1) {
        lnum  += __shfl_down_sync(0xFFFFFFFFu, lnum,  off);
        lmask += __shfl_down_sync(0xFFFFFFFFu, lmask, off);
    }
    if (lane == 0) { red_num[warp] = lnum; red_msk[warp] = lmask; }
    __syncthreads();
    if (warp == 0) {
        float n = (lane < NTHREADS / 32) ? red_num[lane] : 0.0f;
        float m = (lane < NTHREADS / 32) ? red_msk[lane] : 0.0f;
        #pragma unroll
        for (int off = 8; off > 0; off >>= 1) {
            n += __shfl_down_sync(0xFFFFFFFFu, n, off);
            m += __shfl_down_sync(0xFFFFFFFFu, m, off);
        }
        if (lane == 0) { g_pnum[b] = n; g_pmask[b] = m; }
    }
}

__global__ __launch_bounds__(256) void fwd_loss_finalize(float* __restrict__ out) {
    __shared__ float red_num[8];
    __shared__ float red_msk[8];
    const int tid = threadIdx.x;
    float n = g_pnum[tid];   // B_ == 256 == blockDim
    float m = g_pmask[tid];
    const int lane = tid & 31;
    const int warp = tid >> 5;
    #pragma unroll
    for (int off = 16; off > 0; off >>= 1) {
        n += __shfl_down_sync(0xFFFFFFFFu, n, off);
        m += __shfl_down_sync(0xFFFFFFFFu, m, off);
    }
    if (lane == 0) { red_num[warp] = n; red_msk[warp] = m; }
    __syncthreads();
    if (warp == 0) {
        float nn = (lane < 8) ? red_num[lane] : 0.0f;
        float mm = (lane < 8) ? red_msk[lane] : 0.0f;
        #pragma unroll
        for (int off = 4; off > 0; off >>= 1) {
            nn += __shfl_down_sync(0xFFFFFFFFu, nn, off);
            mm += __shfl_down_sync(0xFFFFFFFFu, mm, off);
        }
        if (lane == 0) out[0] = nn / (2.0f * mm + 0.0001f);
    }
}

extern "C" void kernel_launch(void* const* d_in, const int* in_sizes, int n_in,
                              void* d_out, int out_size) {
    const float* flow   = (const float*)d_in[0];
    const float* mask   = (const float*)d_in[1];
    const int*   index  = (const int*)  d_in[2];
    const int*   ids    = (const int*)  d_in[3];
    const int*   index2 = (const int*)  d_in[4];
    const int*   ids2   = (const int*)  d_in[5];
    float* out = (float*)d_out;

    fwd_loss_main<<<B_, NTHREADS>>>(flow, mask, index, ids, index2, ids2);
    fwd_loss_finalize<<<1, 256>>>(out);
}

// round 2
// speedup vs baseline: 1.1429x; 1.1429x over previous
#include <cuda_runtime.h>
#include <cuda_bf16.h>

#define B_  256
#define K_  500
#define H_  152
#define W_  272
#define HW_ (H_ * W_)
#define HASH_SIZE 1024
#define NTHREADS 512
#define ID_MASK  ((1 << 18) - 1)

__device__ float    g_pnum[B_];
__device__ float    g_pmask[B_];
__device__ unsigned g_count = 0;

__device__ __forceinline__ unsigned hash_id(int id) {
    return ((unsigned)id * 2654435761u) & (HASH_SIZE - 1);
}

__global__ __launch_bounds__(NTHREADS) void fwd_loss_fused(
    const float* __restrict__ flow,   // [B,2,H,W]
    const float* __restrict__ mask,   // [B,K]
    const int*   __restrict__ index,  // [B,K]
    const int*   __restrict__ ids,    // [B,K]
    const int*   __restrict__ index2, // [B,K]
    const int*   __restrict__ ids2,   // [B,K]
    float*       __restrict__ out)
{
    __shared__ int    hpack[HASH_SIZE];       // (k<<18) | id ; 0 = empty
    __shared__ float2 sxy[K_];                // precomputed flow*mask per position k
    __shared__ float  red_num[NTHREADS / 32];
    __shared__ float  red_msk[NTHREADS / 32];

    const int b   = blockIdx.x;
    const int tid = threadIdx.x;

    // hash init (runs while the global loads below are in flight)
    #pragma unroll
    for (int i = tid; i < HASH_SIZE; i += NTHREADS) hpack[i] = 0;

    // ---- Phase A: issue ALL global loads up front (one latency epoch) ----
    int   id = 0, id2 = 0, i2 = 0, p = 0;
    float m = 0.0f;
    float px = 0.0f, py = 0.0f;
    if (tid < K_) {
        const int g = b * K_ + tid;
        id  = ids[g];
        p   = index[g];
        m   = mask[g];
        id2 = ids2[g];
        i2  = index2[g];
        const float* fb = flow + (size_t)b * 2 * HW_;
        px = fb[p] * m;          // channel 0, gather
        py = fb[HW_ + p] * m;    // channel 1, gather
    }
    __syncthreads();  // hash init complete

    if (tid < K_) {
        sxy[tid] = make_float2(px, py);
        int packed = (tid << 18) | id;        // id in 1..20000, nonzero
        unsigned slot = hash_id(id);
        while (atomicCAS(&hpack[slot], 0, packed) != 0)
            slot = (slot + 1) & (HASH_SIZE - 1);
    }
    __syncthreads();

    // ---- Phase B: probe + accumulate (shared memory only) ----
    float lnum = 0.0f, lmask = m;   // mask sum uses this thread's own mask[j]
    if (tid < K_ && id2 != 0) {
        unsigned slot = hash_id(id2);
        int x = -1;
        while (true) {
            int pk = hpack[slot];
            if (pk == 0) break;                       // absent (e.g. +100000 ids)
            if ((pk & ID_MASK) == id2) { x = pk >> 18; break; }
            slot = (slot + 1) & (HASH_SIZE - 1);
        }
        if (x >= 0) {
            float2 s  = sxy[x];
            float  vx = (float)(i2 % W_);
            float  vy = (float)i2 / (float)W_;
            lnum = fabsf(s.x - vx) + fabsf(s.y - vy);
        }
    }

    // ---- Block reduction ----
    const int lane = tid & 31;
    const int warp = tid >> 5;
    #pragma unroll
    for (int off = 16; off > 0; off >>= 1) {
        lnum  += __shfl_down_sync(0xFFFFFFFFu, lnum,  off);
        lmask += __shfl_down_sync(0xFFFFFFFFu, lmask, off);
    }
    if (lane == 0) { red_num[warp] = lnum; red_msk[warp] = lmask; }
    __syncthreads();

    __shared__ bool s_last;
    if (tid == 0) {
        float n = 0.0f, mm = 0.0f;
        #pragma unroll
        for (int w = 0; w < NTHREADS / 32; w++) { n += red_num[w]; mm += red_msk[w]; }
        g_pnum[b]  = n;
        g_pmask[b] = mm;
        __threadfence();
        unsigned prev = atomicAdd(&g_count, 1u);
        s_last = (prev == B_ - 1);
    }
    __syncthreads();

    // ---- Last block: final deterministic reduction over 256 partials ----
    if (s_last) {
        __threadfence();
        float n = 0.0f, mm = 0.0f;
        if (tid < B_) { n = g_pnum[tid]; mm = g_pmask[tid]; }
        #pragma unroll
        for (int off = 16; off > 0; off >>= 1) {
            n  += __shfl_down_sync(0xFFFFFFFFu, n,  off);
            mm += __shfl_down_sync(0xFFFFFFFFu, mm, off);
        }
        if (lane == 0) { red_num[warp] = n; red_msk[warp] = mm; }
        __syncthreads();
        if (tid == 0) {
            float nn = 0.0f, mt = 0.0f;
            #pragma unroll
            for (int w = 0; w < B_ / 32; w++) { nn += red_num[w]; mt += red_msk[w]; }
            out[0]  = nn / (2.0f * mt + 0.0001f);
            g_count = 0;   // reset for next graph replay (deterministic)
        }
    }
}

extern "C" void kernel_launch(void* const* d_in, const int* in_sizes, int n_in,
                              void* d_out, int out_size) {
    const float* flow   = (const float*)d_in[0];
    const float* mask   = (const float*)d_in[1];
    const int*   index  = (const int*)  d_in[2];
    const int*   ids    = (const int*)  d_in[3];
    const int*   index2 = (const int*)  d_in[4];
    const int*   ids2   = (const int*)  d_in[5];
    float* out = (float*)d_out;

    fwd_loss_fused<<<B_, NTHREADS>>>(flow, mask, index, ids, index2, ids2, out);
}